// round 14
// baseline (speedup 1.0000x reference)
#include <cuda_runtime.h>
#include <cstdint>

// ---------------- problem constants ----------------
#define BB 2
#define TT 1024
#define EE 1024
#define HH 16
#define DD 64
#define LL 6
#define FF 4096
#define VV 32000
#define RR (BB*TT)   // 2048 token rows

// ---------------- device scratch (static, no allocations) ----------------
__device__ float g_x [RR*EE];
__device__ float g_h [RR*EE];
__device__ float g_q [RR*EE];
__device__ float g_k [RR*EE];
__device__ float g_v [RR*EE];
__device__ float g_o [RR*EE];
__device__ float g_ff[RR*FF];
__device__ float g_S [(size_t)BB*HH*TT*TT];   // attention scores

__device__ __forceinline__ uint32_t smem_u32(const void* p) {
    uint32_t a;
    asm("{ .reg .u64 t; cvta.to.shared.u64 t, %1; cvt.u32.u64 %0, t; }"
        : "=r"(a) : "l"(p));
    return a;
}

#define SW128(o) ((o) ^ (((o) >> 3) & 0x70))

__device__ __forceinline__ void ldsm_x4(uint32_t& r0, uint32_t& r1,
                                        uint32_t& r2, uint32_t& r3, uint32_t addr) {
    asm volatile("ldmatrix.sync.aligned.m8n8.x4.shared.b16 {%0,%1,%2,%3}, [%4];"
                 : "=r"(r0), "=r"(r1), "=r"(r2), "=r"(r3) : "r"(addr));
}

// transposed ldmatrix: for B tiles stored [k][n] (n contiguous)
__device__ __forceinline__ void ldsm_x4_t(uint32_t& r0, uint32_t& r1,
                                          uint32_t& r2, uint32_t& r3, uint32_t addr) {
    asm volatile("ldmatrix.sync.aligned.m8n8.x4.trans.shared.b16 {%0,%1,%2,%3}, [%4];"
                 : "=r"(r0), "=r"(r1), "=r"(r2), "=r"(r3) : "r"(addr));
}

__device__ __forceinline__ void mma_bf16(float& c0, float& c1, float& c2, float& c3,
                                         uint32_t a0, uint32_t a1, uint32_t a2, uint32_t a3,
                                         uint32_t b0, uint32_t b1) {
    asm volatile("mma.sync.aligned.m16n8k16.row.col.f32.bf16.bf16.f32 "
                 "{%0,%1,%2,%3}, {%4,%5,%6,%7}, {%8,%9}, {%0,%1,%2,%3};"
                 : "+f"(c0), "+f"(c1), "+f"(c2), "+f"(c3)
                 : "r"(a0), "r"(a1), "r"(a2), "r"(a3), "r"(b0), "r"(b1));
}

// split two fp32 (consecutive x0,x1) into packed bf16x2 hi and lo
__device__ __forceinline__ void split2(float x0, float x1, uint32_t& h, uint32_t& l) {
    uint32_t hh;
    asm("cvt.rn.bf16x2.f32 %0, %1, %2;" : "=r"(hh) : "f"(x1), "f"(x0));
    float h0 = __uint_as_float(hh << 16);
    float h1 = __uint_as_float(hh & 0xFFFF0000u);
    float l0 = x0 - h0, l1 = x1 - h1;
    uint32_t ll;
    asm("cvt.rn.bf16x2.f32 %0, %1, %2;" : "=r"(ll) : "f"(l1), "f"(l0));
    h = hh; l = ll;
}

// 3 mma terms: ah*bh + ah*bl + al*bh
#define MMA3(ACC, AH, AL, BH0, BH1, BL0, BL1) do { \
    mma_bf16((ACC)[0], (ACC)[1], (ACC)[2], (ACC)[3], \
             (AH)[0], (AH)[1], (AH)[2], (AH)[3], (BH0), (BH1)); \
    mma_bf16((ACC)[0], (ACC)[1], (ACC)[2], (ACC)[3], \
             (AH)[0], (AH)[1], (AH)[2], (AH)[3], (BL0), (BL1)); \
    mma_bf16((ACC)[0], (ACC)[1], (ACC)[2], (ACC)[3], \
             (AL)[0], (AL)[1], (AL)[2], (AL)[3], (BH0), (BH1)); \
} while (0)

// ================= 3xBF16 tensor-core GEMM (fp32-accurate) =================
// C[M,N] = A[M,K] @ B[K,N] (+bias)(+resid)(relu). 128x64 CTA tile, BK=32.
// grid = (M/128, N/64). 128 threads (4 warps, 2x2 of 64x32 warp tiles).
// SMEM/buffer 24KB: Ah@0(8K) [m][k] 64B rows, Al@8K;
//                   Bh@16K(4K) [k][n] 128B rows, Bl@20K. Double: 48KB.
// B loaded coalesced (natural layout) + ldmatrix.trans. 2 CTAs/SM.
#define TG_SMEM 49152

template<bool BIAS, bool RELU, bool RESID>
__global__ void __launch_bounds__(128, 2)
k_tgemm(const float* __restrict__ A, const float* __restrict__ B,
        const float* __restrict__ bias, const float* __restrict__ resid,
        float* __restrict__ C, int M, int N, int K) {
    extern __shared__ char smem[];
    const uint32_t sb = smem_u32(smem);
    const int tid = threadIdx.x, lane = tid & 31, wid = tid >> 5;
    const int wm = wid & 1, wn = wid >> 1;           // 2 x 2 warp grid
    const int rowBase = blockIdx.x * 128;
    const int colBase = blockIdx.y * 64;

    float acc[4][4][4];
    #pragma unroll
    for (int i = 0; i < 4; i++)
        #pragma unroll
        for (int j = 0; j < 4; j++)
            #pragma unroll
            for (int r = 0; r < 4; r++) acc[i][j][r] = 0.f;

    const int a_m = tid >> 3, a_kq = tid & 7;        // A: float4 at (a_m + 16i, kq*4)
    const int bg_k = tid >> 4;                       // B: k row = bg_k + 8i
    const int bg_n = (tid & 15) * 4;                 // B: 4 n-consecutive floats

    // A-frag (non-trans) lane offsets
    const int a_m_in = (lane & 7) + ((lane >> 3) & 1) * 8;
    const int a_kb   = ((lane >> 4) & 1) * 16;
    // B-frag (trans) lane offsets: k within 16-step, n within 16-group
    const int bt_k = (lane & 7) + ((lane >> 3) & 1) * 8;
    const int bt_n = ((lane >> 4) & 1) * 8;

    const int nchunk = K >> 5;
    float4 pa[8], pb[2];

    {
        #pragma unroll
        for (int i = 0; i < 8; i++) {
            int m = a_m + 16 * i;
            pa[i] = *(const float4*)(A + (size_t)(rowBase + m) * K + a_kq * 4);
        }
        #pragma unroll
        for (int i = 0; i < 2; i++) {
            int kk = bg_k + 8 * i;
            pb[i] = *(const float4*)(B + (size_t)kk * N + colBase + bg_n);
        }
        // note: 128 threads * 2 float4 = 256 float4 = 32x64 tile needs 512.
        // Each thread handles rows bg_k+8i for i<2 AND i<2 with second half via +16:
        // use 4 loads instead:
        float4 pb2[2];
        #pragma unroll
        for (int i = 0; i < 2; i++) {
            int kk = bg_k + 8 * i + 16;
            pb2[i] = *(const float4*)(B + (size_t)kk * N + colBase + bg_n);
        }
        #pragma unroll
        for (int i = 0; i < 8; i++) {
            int m = a_m + 16 * i;
            uint32_t h01, l01, h23, l23;
            split2(pa[i].x, pa[i].y, h01, l01);
            split2(pa[i].z, pa[i].w, h23, l23);
            uint32_t off = (uint32_t)(m * 64 + ((a_kq * 8) ^ (((m >> 1) & 3) << 4)));
            *(uint2*)(smem + off)        = make_uint2(h01, h23);
            *(uint2*)(smem + 8192 + off) = make_uint2(l01, l23);
        }
        #pragma unroll
        for (int i = 0; i < 2; i++) {
            int kk = bg_k + 8 * i;
            uint32_t h01, l01, h23, l23;
            split2(pb[i].x, pb[i].y, h01, l01);
            split2(pb[i].z, pb[i].w, h23, l23);
            uint32_t off = SW128((uint32_t)(kk * 128 + bg_n * 2));
            *(uint2*)(smem + 16384 + off) = make_uint2(h01, h23);
            *(uint2*)(smem + 20480 + off) = make_uint2(l01, l23);
        }
        #pragma unroll
        for (int i = 0; i < 2; i++) {
            int kk = bg_k + 8 * i + 16;
            uint32_t h01, l01, h23, l23;
            split2(pb2[i].x, pb2[i].y, h01, l01);
            split2(pb2[i].z, pb2[i].w, h23, l23);
            uint32_t off = SW128((uint32_t)(kk * 128 + bg_n * 2));
            *(uint2*)(smem + 16384 + off) = make_uint2(h01, h23);
            *(uint2*)(smem + 20480 + off) = make_uint2(l01, l23);
        }
    }
    __syncthreads();

    float4 pbA[4];   // 4 B float4 per thread for steady-state prefetch
    for (int c = 0; c < nchunk; c++) {
        const uint32_t base = sb + (uint32_t)(c & 1) * 24576;
        const uint32_t ah = base, al = base + 8192;
        const uint32_t bh = base + 16384, bl = base + 20480;

        if (c + 1 < nchunk) {
            int k0 = (c + 1) << 5;
            #pragma unroll
            for (int i = 0; i < 8; i++) {
                int m = a_m + 16 * i;
                pa[i] = *(const float4*)(A + (size_t)(rowBase + m) * K + k0 + a_kq * 4);
            }
            #pragma unroll
            for (int i = 0; i < 4; i++) {
                int kk = bg_k + 8 * i;
                pbA[i] = *(const float4*)(B + (size_t)(k0 + kk) * N + colBase + bg_n);
            }
        }

        #pragma unroll
        for (int kt = 0; kt < 2; kt++) {
            uint32_t afh[4][4], afl[4][4], bfh[4], bfl[4];
            #pragma unroll
            for (int mt = 0; mt < 4; mt++) {
                int row = wm * 64 + mt * 16 + a_m_in;
                uint32_t off = (uint32_t)(row * 64 + ((kt * 32 + a_kb) ^ (((row >> 1) & 3) << 4)));
                ldsm_x4(afh[mt][0], afh[mt][1], afh[mt][2], afh[mt][3], ah + off);
                ldsm_x4(afl[mt][0], afl[mt][1], afl[mt][2], afl[mt][3], al + off);
            }
            // warp covers 32 n: two 16-wide groups -> two trans x4 (hi) + two (lo)
            uint32_t bfh2[4], bfl2[4];
            {
                int kk = kt * 16 + bt_k;
                int nn0 = wn * 32 + bt_n;
                uint32_t off0 = SW128((uint32_t)(kk * 128 + nn0 * 2));
                ldsm_x4_t(bfh[0], bfh[1], bfh[2], bfh[3], bh + off0);
                ldsm_x4_t(bfl[0], bfl[1], bfl[2], bfl[3], bl + off0);
                uint32_t off1 = SW128((uint32_t)(kk * 128 + (nn0 + 16) * 2));
                ldsm_x4_t(bfh2[0], bfh2[1], bfh2[2], bfh2[3], bh + off1);
                ldsm_x4_t(bfl2[0], bfl2[1], bfl2[2], bfl2[3], bl + off1);
            }
            #pragma unroll
            for (int mt = 0; mt < 4; mt++) {
                #pragma unroll
                for (int nt = 0; nt < 2; nt++) {
                    MMA3(acc[mt][nt], afh[mt], afl[mt],
                         bfh[nt * 2], bfh[nt * 2 + 1], bfl[nt * 2], bfl[nt * 2 + 1]);
                }
                #pragma unroll
                for (int nt = 0; nt < 2; nt++) {
                    MMA3(acc[mt][nt + 2], afh[mt], afl[mt],
                         bfh2[nt * 2], bfh2[nt * 2 + 1], bfl2[nt * 2], bfl2[nt * 2 + 1]);
                }
            }
        }

        if (c + 1 < nchunk) {
            char* nb = smem + ((c + 1) & 1) * 24576;
            #pragma unroll
            for (int i = 0; i < 8; i++) {
                int m = a_m + 16 * i;
                uint32_t h01, l01, h23, l23;
                split2(pa[i].x, pa[i].y, h01, l01);
                split2(pa[i].z, pa[i].w, h23, l23);
                uint32_t off = (uint32_t)(m * 64 + ((a_kq * 8) ^ (((m >> 1) & 3) << 4)));
                *(uint2*)(nb + off)        = make_uint2(h01, h23);
                *(uint2*)(nb + 8192 + off) = make_uint2(l01, l23);
            }
            #pragma unroll
            for (int i = 0; i < 4; i++) {
                int kk = bg_k + 8 * i;
                uint32_t h01, l01, h23, l23;
                split2(pbA[i].x, pbA[i].y, h01, l01);
                split2(pbA[i].z, pbA[i].w, h23, l23);
                uint32_t off = SW128((uint32_t)(kk * 128 + bg_n * 2));
                *(uint2*)(nb + 16384 + off) = make_uint2(h01, h23);
                *(uint2*)(nb + 20480 + off) = make_uint2(l01, l23);
            }
            __syncthreads();
        }
    }

    const int row0 = lane >> 2, col0 = (lane & 3) * 2;
    #pragma unroll
    for (int mt = 0; mt < 4; mt++) {
        #pragma unroll
        for (int nt = 0; nt < 4; nt++) {
            // n-tile order: nt 0,1 -> group0 (n 0..15), nt 2,3 -> group1 (n 16..31)
            int gm = rowBase + wm * 64 + mt * 16 + row0;
            int gn = colBase + wn * 32 + (nt >> 1) * 16 + (nt & 1) * 8 + col0;
            float o0 = acc[mt][nt][0], o1 = acc[mt][nt][1];
            float o2 = acc[mt][nt][2], o3 = acc[mt][nt][3];
            if (BIAS) {
                float bv0 = bias[gn], bv1 = bias[gn + 1];
                o0 += bv0; o1 += bv1; o2 += bv0; o3 += bv1;
            }
            size_t p0 = (size_t)gm * N + gn;
            size_t p1 = (size_t)(gm + 8) * N + gn;
            if (RESID) {
                float2 r0v = *(const float2*)(resid + p0);
                float2 r1v = *(const float2*)(resid + p1);
                o0 += r0v.x; o1 += r0v.y; o2 += r1v.x; o3 += r1v.y;
            }
            if (RELU) {
                o0 = fmaxf(o0, 0.f); o1 = fmaxf(o1, 0.f);
                o2 = fmaxf(o2, 0.f); o3 = fmaxf(o3, 0.f);
            }
            *(float2*)(C + p0) = make_float2(o0, o1);
            *(float2*)(C + p1) = make_float2(o2, o3);
        }
    }
}

// ================= tensor-core attention scores (unchanged) =================
#define SC_SMEM 65536

__global__ void __launch_bounds__(512, 1)
k_scores_t(const float* __restrict__ q, const float* __restrict__ k) {
    const int bh = blockIdx.z, b = bh >> 4, h = bh & 15;
    const int q0 = blockIdx.y * 128, k0 = blockIdx.x * 128;
    if (k0 > q0 + 127) return;

    extern __shared__ char smem[];
    const uint32_t sb = smem_u32(smem);
    const int tid = threadIdx.x, lane = tid & 31, wid = tid >> 5;
    const int wm = wid & 3, wn = wid >> 2;

    {
        #pragma unroll
        for (int i = 0; i < 4; i++) {
            int idx = tid + 512 * i;
            int row = idx >> 4, dq = idx & 15;
            float4 v = *(const float4*)(q + (size_t)(b * TT + q0 + row) * EE + h * DD + dq * 4);
            uint32_t h01, l01, h23, l23;
            split2(v.x, v.y, h01, l01);
            split2(v.z, v.w, h23, l23);
            uint32_t off = (uint32_t)(row * 128 + ((dq * 8) ^ ((row & 7) << 4)));
            *(uint2*)(smem + off)         = make_uint2(h01, h23);
            *(uint2*)(smem + 16384 + off) = make_uint2(l01, l23);
        }
        #pragma unroll
        for (int i = 0; i < 4; i++) {
            int idx = tid + 512 * i;
            int row = idx >> 4, dq = idx & 15;
            float4 v = *(const float4*)(k + (size_t)(b * TT + k0 + row) * EE + h * DD + dq * 4);
            uint32_t h01, l01, h23, l23;
            split2(v.x, v.y, h01, l01);
            split2(v.z, v.w, h23, l23);
            uint32_t off = (uint32_t)(row * 128 + ((dq * 8) ^ ((row & 7) << 4)));
            *(uint2*)(smem + 32768 + off) = make_uint2(h01, h23);
            *(uint2*)(smem + 49152 + off) = make_uint2(l01, l23);
        }
    }
    __syncthreads();

    const int a_m_in = (lane & 7) + ((lane >> 3) & 1) * 8;
    const int a_kb   = ((lane >> 4) & 1) * 16;
    const int b_n_in = (lane & 7) + ((lane >> 4) & 1) * 8;
    const int b_kb   = ((lane >> 3) & 1) * 16;

    float acc[2][4][4];
    #pragma unroll
    for (int i = 0; i < 2; i++)
        #pragma unroll
        for (int j = 0; j < 4; j++)
            #pragma unroll
            for (int r = 0; r < 4; r++) acc[i][j][r] = 0.f;

    #pragma unroll
    for (int kt = 0; kt < 4; kt++) {
        uint32_t afh[2][4], afl[2][4], bfh[2][4], bfl[2][4];
        #pragma unroll
        for (int mt = 0; mt < 2; mt++) {
            int row = wm * 32 + mt * 16 + a_m_in;
            uint32_t off = (uint32_t)(row * 128 + ((kt * 32 + a_kb) ^ ((row & 7) << 4)));
            ldsm_x4(afh[mt][0], afh[mt][1], afh[mt][2], afh[mt][3], sb + off);
            ldsm_x4(afl[mt][0], afl[mt][1], afl[mt][2], afl[mt][3], sb + 16384 + off);
        }
        #pragma unroll
        for (int ntp = 0; ntp < 2; ntp++) {
            int row = wn * 32 + ntp * 16 + b_n_in;
            uint32_t off = (uint32_t)(row * 128 + ((kt * 32 + b_kb) ^ ((row & 7) << 4)));
            ldsm_x4(bfh[ntp][0], bfh[ntp][1], bfh[ntp][2], bfh[ntp][3], sb + 32768 + off);
            ldsm_x4(bfl[ntp][0], bfl[ntp][1], bfl[ntp][2], bfl[ntp][3], sb + 49152 + off);
        }
        #pragma unroll
        for (int mt = 0; mt < 2; mt++)
            #pragma unroll
            for (int nt = 0; nt < 4; nt++) {
                const int np = nt >> 1, ne = (nt & 1) * 2;
                MMA3(acc[mt][nt], afh[mt], afl[mt],
                     bfh[np][ne], bfh[np][ne + 1], bfl[np][ne], bfl[np][ne + 1]);
            }
    }

    const int row0 = lane >> 2, col0 = (lane & 3) * 2;
    #pragma unroll
    for (int mt = 0; mt < 2; mt++) {
        #pragma unroll
        for (int nt = 0; nt < 4; nt++) {
            int qi = q0 + wm * 32 + mt * 16 + row0;
            int kj = k0 + wn * 32 + nt * 8 + col0;
            float s0 = (kj     <= qi) ? acc[mt][nt][0] * 0.125f : -1e30f;
            float s1 = (kj + 1 <= qi) ? acc[mt][nt][1] * 0.125f : -1e30f;
            float s2 = (kj     <= qi + 8) ? acc[mt][nt][2] * 0.125f : -1e30f;
            float s3 = (kj + 1 <= qi + 8) ? acc[mt][nt][3] * 0.125f : -1e30f;
            *(float2*)(g_S + ((size_t)bh * TT + qi) * TT + kj)       = make_float2(s0, s1);
            *(float2*)(g_S + ((size_t)bh * TT + qi + 8) * TT + kj)   = make_float2(s2, s3);
        }
    }
}

// ================= tensor-core O = P @ V =================
// V loaded coalesced (natural [k][d] layout) + ldmatrix.trans.
#define AV_SMEM 49152

__global__ void __launch_bounds__(256, 2)
k_av_t(const float* __restrict__ v, float* __restrict__ o) {
    extern __shared__ char smem[];
    const uint32_t sb = smem_u32(smem);
    const int bh = blockIdx.y, b = bh >> 4, h = bh & 15;
    const int q0 = blockIdx.x * 128;
    const int tid = threadIdx.x, lane = tid & 31, wid = tid >> 5;
    const int wm = wid & 3, wn = wid >> 2;

    const int a_m = tid >> 3, a_kq = tid & 7;
    const int vg_k = tid >> 4;                 // 0..15, +16 for second half
    const int vg_n = (tid & 15) * 4;

    const int a_m_in = (lane & 7) + ((lane >> 3) & 1) * 8;
    const int a_kb   = ((lane >> 4) & 1) * 16;
    const int bt_k = (lane & 7) + ((lane >> 3) & 1) * 8;
    const int bt_n = ((lane >> 4) & 1) * 8;

    float acc[2][4][4];
    #pragma unroll
    for (int i = 0; i < 2; i++)
        #pragma unroll
        for (int j = 0; j < 4; j++)
            #pragma unroll
            for (int r = 0; r < 4; r++) acc[i][j][r] = 0.f;

    const int nchunk = (q0 + 128) >> 5;
    const float* Prow = g_S + ((size_t)bh * TT + q0) * TT;
    float4 pa[4], pb[2];

    {
        #pragma unroll
        for (int i = 0; i < 4; i++) {
            int idx = tid + 256 * i;
            int m = idx >> 3, kq = idx & 7;
            pa[i] = *(const float4*)(Prow + (size_t)m * TT + kq * 4);
        }
        #pragma unroll
        for (int i = 0; i < 2; i++) {
            int kk = vg_k + 16 * i;
            pb[i] = *(const float4*)(v + (size_t)(b * TT + kk) * EE + h * DD + vg_n);
        }
        #pragma unroll
        for (int i = 0; i < 4; i++) {
            int idx = tid + 256 * i;
            int m = idx >> 3, kq = idx & 7;
            uint32_t h01, l01, h23, l23;
            split2(pa[i].x, pa[i].y, h01, l01);
            split2(pa[i].z, pa[i].w, h23, l23);
            uint32_t off = (uint32_t)(m * 64 + ((kq * 8) ^ (((m >> 1) & 3) << 4)));
            *(uint2*)(smem + off)        = make_uint2(h01, h23);
            *(uint2*)(smem + 8192 + off) = make_uint2(l01, l23);
        }
        #pragma unroll
        for (int i = 0; i < 2; i++) {
            int kk = vg_k + 16 * i;
            uint32_t h01, l01, h23, l23;
            split2(pb[i].x, pb[i].y, h01, l01);
            split2(pb[i].z, pb[i].w, h23, l23);
            uint32_t off = SW128((uint32_t)(kk * 128 + vg_n * 2));
            *(uint2*)(smem + 16384 + off) = make_uint2(h01, h23);
            *(uint2*)(smem + 20480 + off) = make_uint2(l01, l23);
        }
    }
    __syncthreads();

    for (int c = 0; c < nchunk; c++) {
        const uint32_t base = sb + (uint32_t)(c & 1) * 24576;
        const uint32_t ph = base, pl = base + 8192;
        const uint32_t vh = base + 16384, vl = base + 20480;

        if (c + 1 < nchunk) {
            int j0 = (c + 1) << 5;
            #pragma unroll
            for (int i = 0; i < 4; i++) {
                int idx = tid + 256 * i;
                int m = idx >> 3, kq = idx & 7;
                pa[i] = *(const float4*)(Prow + (size_t)m * TT + j0 + kq * 4);
            }
            #pragma unroll
            for (int i = 0; i < 2; i++) {
                int kk = vg_k + 16 * i;
                pb[i] = *(const float4*)(v + (size_t)(b * TT + j0 + kk) * EE + h * DD + vg_n);
            }
        }

        #pragma unroll
        for (int kt = 0; kt < 2; kt++) {
            uint32_t afh[2][4], afl[2][4], bfh[4], bfl[4], bfh2[4], bfl2[4];
            #pragma unroll
            for (int mt = 0; mt < 2; mt++) {
                int row = wm * 32 + mt * 16 + a_m_in;
                uint32_t off = (uint32_t)(row * 64 + ((kt * 32 + a_kb) ^ (((row >> 1) & 3) << 4)));
                ldsm_x4(afh[mt][0], afh[mt][1], afh[mt][2], afh[mt][3], ph + off);
                ldsm_x4(afl[mt][0], afl[mt][1], afl[mt][2], afl[mt][3], pl + off);
            }
            {
                int kk = kt * 16 + bt_k;
                int nn0 = wn * 32 + bt_n;
                uint32_t off0 = SW128((uint32_t)(kk * 128 + nn0 * 2));
                ldsm_x4_t(bfh[0], bfh[1], bfh[2], bfh[3], vh + off0);
                ldsm_x4_t(bfl[0], bfl[1], bfl[2], bfl[3], vl + off0);
                uint32_t off1 = SW128((uint32_t)(kk * 128 + (nn0 + 16) * 2));
                ldsm_x4_t(bfh2[0], bfh2[1], bfh2[2], bfh2[3], vh + off1);
                ldsm_x4_t(bfl2[0], bfl2[1], bfl2[2], bfl2[3], vl + off1);
            }
            #pragma unroll
            for (int mt = 0; mt < 2; mt++) {
                #pragma unroll
                for (int nt = 0; nt < 2; nt++)
                    MMA3(acc[mt][nt], afh[mt], afl[mt],
                         bfh[nt * 2], bfh[nt * 2 + 1], bfl[nt * 2], bfl[nt * 2 + 1]);
                #pragma unroll
                for (int nt = 0; nt < 2; nt++)
                    MMA3(acc[mt][nt + 2], afh[mt], afl[mt],
                         bfh2[nt * 2], bfh2[nt * 2 + 1], bfl2[nt * 2], bfl2[nt * 2 + 1]);
            }
        }

        if (c + 1 < nchunk) {
            char* nb = smem + ((c + 1) & 1) * 24576;
            #pragma unroll
            for (int i = 0; i < 4; i++) {
                int idx = tid + 256 * i;
                int m = idx >> 3, kq = idx & 7;
                uint32_t h01, l01, h23, l23;
                split2(pa[i].x, pa[i].y, h01, l01);
                split2(pa[i].z, pa[i].w, h23, l23);
                uint32_t off = (uint32_t)(m * 64 + ((kq * 8) ^ (((m >> 1) & 3) << 4)));
                *(uint2*)(nb + off)        = make_uint2(h01, h23);
                *(uint2*)(nb + 8192 + off) = make_uint2(l01, l23);
            }
            #pragma unroll
            for (int i = 0; i < 2; i++) {
                int kk = vg_k + 16 * i;
                uint32_t h01, l01, h23, l23;
                split2(pb[i].x, pb[i].y, h01, l01);
                split2(pb[i].z, pb[i].w, h23, l23);
                uint32_t off = SW128((uint32_t)(kk * 128 + vg_n * 2));
                *(uint2*)(nb + 16384 + off) = make_uint2(h01, h23);
                *(uint2*)(nb + 20480 + off) = make_uint2(l01, l23);
            }
            __syncthreads();
        }
    }

    const int row0 = lane >> 2, col0 = (lane & 3) * 2;
    #pragma unroll
    for (int mt = 0; mt < 2; mt++) {
        #pragma unroll
        for (int nt = 0; nt < 4; nt++) {
            int gm = q0 + wm * 32 + mt * 16 + row0;
            int gn = wn * 32 + (nt >> 1) * 16 + (nt & 1) * 8 + col0;
            size_t p0 = (size_t)(b * TT + gm) * EE + h * DD + gn;
            size_t p1 = (size_t)(b * TT + gm + 8) * EE + h * DD + gn;
            *(float2*)(o + p0) = make_float2(acc[mt][nt][0], acc[mt][nt][1]);
            *(float2*)(o + p1) = make_float2(acc[mt][nt][2], acc[mt][nt][3]);
        }
    }
}

// ---------------- embed ----------------
__global__ void k_embed(const int* __restrict__ idx, const float* __restrict__ tok,
                        const float* __restrict__ pos, float* __restrict__ x) {
    int r = blockIdx.x;
    int t = r & (TT - 1);
    int tokid = idx[r];
    const float4* te = (const float4*)(tok + (size_t)tokid * EE);
    const float4* pe = (const float4*)(pos + (size_t)t * EE);
    float4* xr = (float4*)(x + (size_t)r * EE);
    int c = threadIdx.x;
    float4 a = te[c], b = pe[c];
    xr[c] = make_float4(a.x + b.x, a.y + b.y, a.z + b.z, a.w + b.w);
}

// ---------------- block reduce ----------------
__device__ __forceinline__ float blockReduceSum(float val, float* red) {
    int tid = threadIdx.x;
    #pragma unroll
    for (int o = 16; o; o >>= 1) val += __shfl_xor_sync(0xffffffffu, val, o);
    if ((tid & 31) == 0) red[tid >> 5] = val;
    __syncthreads();
    if (tid < 32) {
        float v = (tid < 8) ? red[tid] : 0.f;
        #pragma unroll
        for (int o = 4; o; o >>= 1) v += __shfl_xor_sync(0xffffffffu, v, o);
        if (tid == 0) red[0] = v;
    }
    __syncthreads();
    float r = red[0];
    __syncthreads();
    return r;
}

// ---------------- layernorm ----------------
__global__ void k_ln(const float* __restrict__ x, const float* __restrict__ g,
                     const float* __restrict__ b, float* __restrict__ out) {
    __shared__ float red[32];
    int row = blockIdx.x, tid = threadIdx.x;
    const float* xr = x + (size_t)row * EE;
    float v[4];
    float s = 0.f;
    #pragma unroll
    for (int i = 0; i < 4; i++) { v[i] = xr[tid + 256 * i]; s += v[i]; }
    s = blockReduceSum(s, red);
    float mean = s * (1.f / EE);
    float s2 = 0.f;
    #pragma unroll
    for (int i = 0; i < 4; i++) { float d = v[i] - mean; s2 += d * d; }
    s2 = blockReduceSum(s2, red);
    float inv = rsqrtf(s2 * (1.f / EE) + 1e-5f);
    #pragma unroll
    for (int i = 0; i < 4; i++) {
        int c = tid + 256 * i;
        out[(size_t)row * EE + c] = (v[i] - mean) * inv * g[c] + b[c];
    }
}

// ---------------- softmax per row (variable length) ----------------
__global__ void k_softmax() {
    __shared__ float red[32];
    int row = blockIdx.x;
    int qpos = row & (TT - 1);
    int L = (qpos | 127) + 1;
    float* r = g_S + (size_t)row * TT;
    int tid = threadIdx.x;
    float v[4], m = -1e30f;
    #pragma unroll
    for (int i = 0; i < 4; i++) {
        int c = tid + 256 * i;
        v[i] = (c < L) ? r[c] : -1e30f;
        m = fmaxf(m, v[i]);
    }
    #pragma unroll
    for (int o = 16; o; o >>= 1) m = fmaxf(m, __shfl_xor_sync(0xffffffffu, m, o));
    if ((tid & 31) == 0) red[tid >> 5] = m;
    __syncthreads();
    if (tid < 32) {
        float t = (tid < 8) ? red[tid] : -1e30f;
        #pragma unroll
        for (int o = 4; o; o >>= 1) t = fmaxf(t, __shfl_xor_sync(0xffffffffu, t, o));
        if (tid == 0) red[0] = t;
    }
    __syncthreads();
    m = red[0];
    __syncthreads();
    float s = 0.f;
    #pragma unroll
    for (int i = 0; i < 4; i++) { v[i] = __expf(v[i] - m); s += v[i]; }
    s = blockReduceSum(s, red);
    float inv = 1.f / s;
    #pragma unroll
    for (int i = 0; i < 4; i++) {
        int c = tid + 256 * i;
        if (c < L) r[c] = v[i] * inv;
    }
}

// ---------------- host orchestration ----------------
extern "C" void kernel_launch(void* const* d_in, const int* in_sizes, int n_in,
                              void* d_out, int out_size) {
    const int*   idx  = (const int*)  d_in[0];
    const float* tok  = (const float*)d_in[1];
    const float* pos  = (const float*)d_in[2];
    const float* Wq   = (const float*)d_in[3];
    const float* Wk   = (const float*)d_in[4];
    const float* Wv   = (const float*)d_in[5];
    const float* Wp   = (const float*)d_in[6];
    const float* bp   = (const float*)d_in[7];
    const float* g1   = (const float*)d_in[8];
    const float* b1   = (const float*)d_in[9];
    const float* g2   = (const float*)d_in[10];
    const float* b2   = (const float*)d_in[11];
    const float* W1   = (const float*)d_in[12];
    const float* bf1  = (const float*)d_in[13];
    const float* W2   = (const float*)d_in[14];
    const float* bf2  = (const float*)d_in[15];
    const float* gf   = (const float*)d_in[16];
    const float* bff  = (const float*)d_in[17];
    const float* Wlm  = (const float*)d_in[18];
    const float* blm  = (const float*)d_in[19];
    float* out = (float*)d_out;

    float *x, *h, *q, *k, *v, *o, *ff;
    cudaGetSymbolAddress((void**)&x,  g_x);
    cudaGetSymbolAddress((void**)&h,  g_h);
    cudaGetSymbolAddress((void**)&q,  g_q);
    cudaGetSymbolAddress((void**)&k,  g_k);
    cudaGetSymbolAddress((void**)&v,  g_v);
    cudaGetSymbolAddress((void**)&o,  g_o);
    cudaGetSymbolAddress((void**)&ff, g_ff);

    cudaFuncSetAttribute(k_tgemm<false,false,false>,
                         cudaFuncAttributeMaxDynamicSharedMemorySize, TG_SMEM);
    cudaFuncSetAttribute(k_tgemm<true,false,true>,
                         cudaFuncAttributeMaxDynamicSharedMemorySize, TG_SMEM);
    cudaFuncSetAttribute(k_tgemm<true,true,false>,
                         cudaFuncAttributeMaxDynamicSharedMemorySize, TG_SMEM);
    cudaFuncSetAttribute(k_tgemm<true,false,false>,
                         cudaFuncAttributeMaxDynamicSharedMemorySize, TG_SMEM);
    cudaFuncSetAttribute(k_scores_t,
                         cudaFuncAttributeMaxDynamicSharedMemorySize, SC_SMEM);
    cudaFuncSetAttribute(k_av_t,
                         cudaFuncAttributeMaxDynamicSharedMemorySize, AV_SMEM);

    k_embed<<<RR, 256>>>(idx, tok, pos, x);

    dim3 gEE(RR / 128, EE / 64);       // (16, 16)
    dim3 gFF(RR / 128, FF / 64);       // (16, 64)
    dim3 gLM(RR / 128, VV / 64);       // (16, 500)

    for (int l = 0; l < LL; l++) {
        const float* wq = Wq + (size_t)l * EE * EE;
        const float* wk = Wk + (size_t)l * EE * EE;
        const float* wv = Wv + (size_t)l * EE * EE;
        const float* wp = Wp + (size_t)l * EE * EE;
        const float* w1 = W1 + (size_t)l * EE * FF;
        const float* w2 = W2 + (size_t)l * FF * EE;

        k_ln<<<RR, 256>>>(x, g1 + l * EE, b1 + l * EE, h);
        k_tgemm<false,false,false><<<gEE, 128, TG_SMEM>>>(h, wq, nullptr, nullptr, q, RR, EE, EE);
        k_tgemm<false,false,false><<<gEE, 128, TG_SMEM>>>(h, wk, nullptr, nullptr, k, RR, EE, EE);
        k_tgemm<false,false,false><<<gEE, 128, TG_SMEM>>>(h, wv, nullptr, nullptr, v, RR, EE, EE);

        k_scores_t<<<dim3(8, 8, 32), 512, SC_SMEM>>>(q, k);
        k_softmax<<<BB * HH * TT, 256>>>();
        k_av_t<<<dim3(8, 32), 256, AV_SMEM>>>(v, o);

        k_tgemm<true,false,true><<<gEE, 128, TG_SMEM>>>(o, wp, bp + l * EE, x, x, RR, EE, EE);

        k_ln<<<RR, 256>>>(x, g2 + l * EE, b2 + l * EE, h);
        k_tgemm<true,true,false><<<gFF, 128, TG_SMEM>>>(h, w1, bf1 + l * FF, nullptr, ff, RR, FF, EE);
        k_tgemm<true,false,true><<<gEE, 128, TG_SMEM>>>(ff, w2, bf2 + l * EE, x, x, RR, EE, FF);
    }

    k_ln<<<RR, 256>>>(x, gf, bff, h);
    k_tgemm<true,false,false><<<gLM, 128, TG_SMEM>>>(h, Wlm, blm, nullptr, out, RR, VV, EE);
}

// round 15
// speedup vs baseline: 1.0172x; 1.0172x over previous
#include <cuda_runtime.h>
#include <cstdint>

// ---------------- problem constants ----------------
#define BB 2
#define TT 1024
#define EE 1024
#define HH 16
#define DD 64
#define LL 6
#define FF 4096
#define VV 32000
#define RR (BB*TT)   // 2048 token rows

// ---------------- device scratch (static, no allocations) ----------------
__device__ float g_x [RR*EE];
__device__ float g_h [RR*EE];
__device__ float g_q [RR*EE];
__device__ float g_k [RR*EE];
__device__ float g_v [RR*EE];
__device__ float g_o [RR*EE];
__device__ float g_ff[RR*FF];
__device__ float g_S [(size_t)BB*HH*TT*TT];   // attention scores (raw, masked)
__device__ float2 g_st[BB*HH*TT];             // per-row (max, 1/sum) softmax stats

__device__ __forceinline__ uint32_t smem_u32(const void* p) {
    uint32_t a;
    asm("{ .reg .u64 t; cvta.to.shared.u64 t, %1; cvt.u32.u64 %0, t; }"
        : "=r"(a) : "l"(p));
    return a;
}

__device__ __forceinline__ void ldsm_x4(uint32_t& r0, uint32_t& r1,
                                        uint32_t& r2, uint32_t& r3, uint32_t addr) {
    asm volatile("ldmatrix.sync.aligned.m8n8.x4.shared.b16 {%0,%1,%2,%3}, [%4];"
                 : "=r"(r0), "=r"(r1), "=r"(r2), "=r"(r3) : "r"(addr));
}

__device__ __forceinline__ void mma_bf16(float& c0, float& c1, float& c2, float& c3,
                                         uint32_t a0, uint32_t a1, uint32_t a2, uint32_t a3,
                                         uint32_t b0, uint32_t b1) {
    asm volatile("mma.sync.aligned.m16n8k16.row.col.f32.bf16.bf16.f32 "
                 "{%0,%1,%2,%3}, {%4,%5,%6,%7}, {%8,%9}, {%0,%1,%2,%3};"
                 : "+f"(c0), "+f"(c1), "+f"(c2), "+f"(c3)
                 : "r"(a0), "r"(a1), "r"(a2), "r"(a3), "r"(b0), "r"(b1));
}

// split two fp32 (k-consecutive x0,x1) into packed bf16x2 hi and lo
__device__ __forceinline__ void split2(float x0, float x1, uint32_t& h, uint32_t& l) {
    uint32_t hh;
    asm("cvt.rn.bf16x2.f32 %0, %1, %2;" : "=r"(hh) : "f"(x1), "f"(x0));
    float h0 = __uint_as_float(hh << 16);
    float h1 = __uint_as_float(hh & 0xFFFF0000u);
    float l0 = x0 - h0, l1 = x1 - h1;
    uint32_t ll;
    asm("cvt.rn.bf16x2.f32 %0, %1, %2;" : "=r"(ll) : "f"(l1), "f"(l0));
    h = hh; l = ll;
}

// 3 mma terms: ah*bh + ah*bl + al*bh
#define MMA3(ACC, AH, AL, BH0, BH1, BL0, BL1) do { \
    mma_bf16((ACC)[0], (ACC)[1], (ACC)[2], (ACC)[3], \
             (AH)[0], (AH)[1], (AH)[2], (AH)[3], (BH0), (BH1)); \
    mma_bf16((ACC)[0], (ACC)[1], (ACC)[2], (ACC)[3], \
             (AH)[0], (AH)[1], (AH)[2], (AH)[3], (BL0), (BL1)); \
    mma_bf16((ACC)[0], (ACC)[1], (ACC)[2], (ACC)[3], \
             (AL)[0], (AL)[1], (AL)[2], (AL)[3], (BH0), (BH1)); \
} while (0)

// ================= 3xBF16 tensor-core GEMM (R13 version — best measured) ======
// C[M,N] = A[M,K] @ B[K,N] (+bias)(+resid)(relu). 128x64 CTA tile, BK=32.
// grid = (M/128, N/64). 128 threads (4 warps, 2x2 of 64x32 warp tiles).
// SMEM per buffer 24KB: Ah@0(8K), Al@8K, Bh@16K(4K), Bl@20K. Double: 48KB.
#define TG_SMEM 49152

template<bool BIAS, bool RELU, bool RESID>
__global__ void __launch_bounds__(128, 2)
k_tgemm(const float* __restrict__ A, const float* __restrict__ B,
        const float* __restrict__ bias, const float* __restrict__ resid,
        float* __restrict__ C, int M, int N, int K) {
    extern __shared__ char smem[];
    const uint32_t sb = smem_u32(smem);
    const int tid = threadIdx.x, lane = tid & 31, wid = tid >> 5;
    const int wm = wid & 1, wn = wid >> 1;           // 2 x 2 warp grid
    const int rowBase = blockIdx.x * 128;
    const int colBase = blockIdx.y * 64;

    float acc[4][4][4];
    #pragma unroll
    for (int i = 0; i < 4; i++)
        #pragma unroll
        for (int j = 0; j < 4; j++)
            #pragma unroll
            for (int r = 0; r < 4; r++) acc[i][j][r] = 0.f;

    const int a_m = tid >> 3, a_kq = tid & 7;        // A: float4 at (a_m + 16i, kq*4)
    const int b_n = tid & 63, b_q0 = tid >> 6;       // B: col n, kq = (q0+2i)^s
    const int b_s = (b_n >> 3) & 7;

    const int a_m_in = (lane & 7) + ((lane >> 3) & 1) * 8;
    const int a_kb   = ((lane >> 4) & 1) * 16;
    const int b_n_in = (lane & 7) + ((lane >> 4) & 1) * 8;
    const int b_kb   = ((lane >> 3) & 1) * 16;

    const int nchunk = K >> 5;
    float4 pa[8], pb[4];

    {
        #pragma unroll
        for (int i = 0; i < 8; i++) {
            int m = a_m + 16 * i;
            pa[i] = *(const float4*)(A + (size_t)(rowBase + m) * K + a_kq * 4);
        }
        #pragma unroll
        for (int i = 0; i < 4; i++) {
            int kq = (b_q0 + 2 * i) ^ b_s;
            const float* bp = B + (size_t)(kq * 4) * N + colBase + b_n;
            pb[i] = make_float4(bp[0], bp[(size_t)N], bp[(size_t)2 * N], bp[(size_t)3 * N]);
        }
        #pragma unroll
        for (int i = 0; i < 8; i++) {
            int m = a_m + 16 * i;
            uint32_t h01, l01, h23, l23;
            split2(pa[i].x, pa[i].y, h01, l01);
            split2(pa[i].z, pa[i].w, h23, l23);
            uint32_t off = (uint32_t)(m * 64 + ((a_kq * 8) ^ (((m >> 1) & 3) << 4)));
            *(uint2*)(smem + off)        = make_uint2(h01, h23);
            *(uint2*)(smem + 8192 + off) = make_uint2(l01, l23);
        }
        #pragma unroll
        for (int i = 0; i < 4; i++) {
            int kq = (b_q0 + 2 * i) ^ b_s;
            uint32_t h01, l01, h23, l23;
            split2(pb[i].x, pb[i].y, h01, l01);
            split2(pb[i].z, pb[i].w, h23, l23);
            uint32_t off = (uint32_t)(b_n * 64 + ((kq * 8) ^ (((b_n >> 1) & 3) << 4)));
            *(uint2*)(smem + 16384 + off) = make_uint2(h01, h23);
            *(uint2*)(smem + 20480 + off) = make_uint2(l01, l23);
        }
    }
    __syncthreads();

    for (int c = 0; c < nchunk; c++) {
        const uint32_t base = sb + (uint32_t)(c & 1) * 24576;
        const uint32_t ah = base, al = base + 8192;
        const uint32_t bh = base + 16384, bl = base + 20480;

        if (c + 1 < nchunk) {
            int k0 = (c + 1) << 5;
            #pragma unroll
            for (int i = 0; i < 8; i++) {
                int m = a_m + 16 * i;
                pa[i] = *(const float4*)(A + (size_t)(rowBase + m) * K + k0 + a_kq * 4);
            }
            #pragma unroll
            for (int i = 0; i < 4; i++) {
                int kq = (b_q0 + 2 * i) ^ b_s;
                const float* bp = B + (size_t)(k0 + kq * 4) * N + colBase + b_n;
                pb[i] = make_float4(bp[0], bp[(size_t)N], bp[(size_t)2 * N], bp[(size_t)3 * N]);
            }
        }

        #pragma unroll
        for (int kt = 0; kt < 2; kt++) {
            uint32_t afh[4][4], afl[4][4], bfh[2][4], bfl[2][4];
            #pragma unroll
            for (int mt = 0; mt < 4; mt++) {
                int row = wm * 64 + mt * 16 + a_m_in;
                uint32_t off = (uint32_t)(row * 64 + ((kt * 32 + a_kb) ^ (((row >> 1) & 3) << 4)));
                ldsm_x4(afh[mt][0], afh[mt][1], afh[mt][2], afh[mt][3], ah + off);
                ldsm_x4(afl[mt][0], afl[mt][1], afl[mt][2], afl[mt][3], al + off);
            }
            #pragma unroll
            for (int ntp = 0; ntp < 2; ntp++) {
                int row = wn * 32 + ntp * 16 + b_n_in;
                uint32_t off = (uint32_t)(row * 64 + ((kt * 32 + b_kb) ^ (((row >> 1) & 3) << 4)));
                ldsm_x4(bfh[ntp][0], bfh[ntp][1], bfh[ntp][2], bfh[ntp][3], bh + off);
                ldsm_x4(bfl[ntp][0], bfl[ntp][1], bfl[ntp][2], bfl[ntp][3], bl + off);
            }
            #pragma unroll
            for (int mt = 0; mt < 4; mt++)
                #pragma unroll
                for (int nt = 0; nt < 4; nt++) {
                    const int np = nt >> 1, ne = (nt & 1) * 2;
                    MMA3(acc[mt][nt], afh[mt], afl[mt],
                         bfh[np][ne], bfh[np][ne + 1], bfl[np][ne], bfl[np][ne + 1]);
                }
        }

        if (c + 1 < nchunk) {
            char* nb = smem + ((c + 1) & 1) * 24576;
            #pragma unroll
            for (int i = 0; i < 8; i++) {
                int m = a_m + 16 * i;
                uint32_t h01, l01, h23, l23;
                split2(pa[i].x, pa[i].y, h01, l01);
                split2(pa[i].z, pa[i].w, h23, l23);
                uint32_t off = (uint32_t)(m * 64 + ((a_kq * 8) ^ (((m >> 1) & 3) << 4)));
                *(uint2*)(nb + off)        = make_uint2(h01, h23);
                *(uint2*)(nb + 8192 + off) = make_uint2(l01, l23);
            }
            #pragma unroll
            for (int i = 0; i < 4; i++) {
                int kq = (b_q0 + 2 * i) ^ b_s;
                uint32_t h01, l01, h23, l23;
                split2(pb[i].x, pb[i].y, h01, l01);
                split2(pb[i].z, pb[i].w, h23, l23);
                uint32_t off = (uint32_t)(b_n * 64 + ((kq * 8) ^ (((b_n >> 1) & 3) << 4)));
                *(uint2*)(nb + 16384 + off) = make_uint2(h01, h23);
                *(uint2*)(nb + 20480 + off) = make_uint2(l01, l23);
            }
            __syncthreads();
        }
    }

    const int row0 = lane >> 2, col0 = (lane & 3) * 2;
    #pragma unroll
    for (int mt = 0; mt < 4; mt++) {
        #pragma unroll
        for (int nt = 0; nt < 4; nt++) {
            int gm = rowBase + wm * 64 + mt * 16 + row0;
            int gn = colBase + wn * 32 + nt * 8 + col0;
            float o0 = acc[mt][nt][0], o1 = acc[mt][nt][1];
            float o2 = acc[mt][nt][2], o3 = acc[mt][nt][3];
            if (BIAS) {
                float bv0 = bias[gn], bv1 = bias[gn + 1];
                o0 += bv0; o1 += bv1; o2 += bv0; o3 += bv1;
            }
            size_t p0 = (size_t)gm * N + gn;
            size_t p1 = (size_t)(gm + 8) * N + gn;
            if (RESID) {
                float2 r0v = *(const float2*)(resid + p0);
                float2 r1v = *(const float2*)(resid + p1);
                o0 += r0v.x; o1 += r0v.y; o2 += r1v.x; o3 += r1v.y;
            }
            if (RELU) {
                o0 = fmaxf(o0, 0.f); o1 = fmaxf(o1, 0.f);
                o2 = fmaxf(o2, 0.f); o3 = fmaxf(o3, 0.f);
            }
            *(float2*)(C + p0) = make_float2(o0, o1);
            *(float2*)(C + p1) = make_float2(o2, o3);
        }
    }
}

// ================= tensor-core attention scores =================
// Fully-masked tiles (k0 > q0+127) are never read downstream — early return.
#define SC_SMEM 65536

__global__ void __launch_bounds__(512, 1)
k_scores_t(const float* __restrict__ q, const float* __restrict__ k) {
    const int bh = blockIdx.z, b = bh >> 4, h = bh & 15;
    const int q0 = blockIdx.y * 128, k0 = blockIdx.x * 128;
    if (k0 > q0 + 127) return;

    extern __shared__ char smem[];
    const uint32_t sb = smem_u32(smem);
    const int tid = threadIdx.x, lane = tid & 31, wid = tid >> 5;
    const int wm = wid & 3, wn = wid >> 2;

    {
        #pragma unroll
        for (int i = 0; i < 4; i++) {
            int idx = tid + 512 * i;
            int row = idx >> 4, dq = idx & 15;
            float4 v = *(const float4*)(q + (size_t)(b * TT + q0 + row) * EE + h * DD + dq * 4);
            uint32_t h01, l01, h23, l23;
            split2(v.x, v.y, h01, l01);
            split2(v.z, v.w, h23, l23);
            uint32_t off = (uint32_t)(row * 128 + ((dq * 8) ^ ((row & 7) << 4)));
            *(uint2*)(smem + off)         = make_uint2(h01, h23);
            *(uint2*)(smem + 16384 + off) = make_uint2(l01, l23);
        }
        #pragma unroll
        for (int i = 0; i < 4; i++) {
            int idx = tid + 512 * i;
            int row = idx >> 4, dq = idx & 15;
            float4 v = *(const float4*)(k + (size_t)(b * TT + k0 + row) * EE + h * DD + dq * 4);
            uint32_t h01, l01, h23, l23;
            split2(v.x, v.y, h01, l01);
            split2(v.z, v.w, h23, l23);
            uint32_t off = (uint32_t)(row * 128 + ((dq * 8) ^ ((row & 7) << 4)));
            *(uint2*)(smem + 32768 + off) = make_uint2(h01, h23);
            *(uint2*)(smem + 49152 + off) = make_uint2(l01, l23);
        }
    }
    __syncthreads();

    const int a_m_in = (lane & 7) + ((lane >> 3) & 1) * 8;
    const int a_kb   = ((lane >> 4) & 1) * 16;
    const int b_n_in = (lane & 7) + ((lane >> 4) & 1) * 8;
    const int b_kb   = ((lane >> 3) & 1) * 16;

    float acc[2][4][4];
    #pragma unroll
    for (int i = 0; i < 2; i++)
        #pragma unroll
        for (int j = 0; j < 4; j++)
            #pragma unroll
            for (int r = 0; r < 4; r++) acc[i][j][r] = 0.f;

    #pragma unroll
    for (int kt = 0; kt < 4; kt++) {
        uint32_t afh[2][4], afl[2][4], bfh[2][4], bfl[2][4];
        #pragma unroll
        for (int mt = 0; mt < 2; mt++) {
            int row = wm * 32 + mt * 16 + a_m_in;
            uint32_t off = (uint32_t)(row * 128 + ((kt * 32 + a_kb) ^ ((row & 7) << 4)));
            ldsm_x4(afh[mt][0], afh[mt][1], afh[mt][2], afh[mt][3], sb + off);
            ldsm_x4(afl[mt][0], afl[mt][1], afl[mt][2], afl[mt][3], sb + 16384 + off);
        }
        #pragma unroll
        for (int ntp = 0; ntp < 2; ntp++) {
            int row = wn * 32 + ntp * 16 + b_n_in;
            uint32_t off = (uint32_t)(row * 128 + ((kt * 32 + b_kb) ^ ((row & 7) << 4)));
            ldsm_x4(bfh[ntp][0], bfh[ntp][1], bfh[ntp][2], bfh[ntp][3], sb + 32768 + off);
            ldsm_x4(bfl[ntp][0], bfl[ntp][1], bfl[ntp][2], bfl[ntp][3], sb + 49152 + off);
        }
        #pragma unroll
        for (int mt = 0; mt < 2; mt++)
            #pragma unroll
            for (int nt = 0; nt < 4; nt++) {
                const int np = nt >> 1, ne = (nt & 1) * 2;
                MMA3(acc[mt][nt], afh[mt], afl[mt],
                     bfh[np][ne], bfh[np][ne + 1], bfl[np][ne], bfl[np][ne + 1]);
            }
    }

    const int row0 = lane >> 2, col0 = (lane & 3) * 2;
    #pragma unroll
    for (int mt = 0; mt < 2; mt++) {
        #pragma unroll
        for (int nt = 0; nt < 4; nt++) {
            int qi = q0 + wm * 32 + mt * 16 + row0;
            int kj = k0 + wn * 32 + nt * 8 + col0;
            float s0 = (kj     <= qi) ? acc[mt][nt][0] * 0.125f : -1e30f;
            float s1 = (kj + 1 <= qi) ? acc[mt][nt][1] * 0.125f : -1e30f;
            float s2 = (kj     <= qi + 8) ? acc[mt][nt][2] * 0.125f : -1e30f;
            float s3 = (kj + 1 <= qi + 8) ? acc[mt][nt][3] * 0.125f : -1e30f;
            *(float2*)(g_S + ((size_t)bh * TT + qi) * TT + kj)       = make_float2(s0, s1);
            *(float2*)(g_S + ((size_t)bh * TT + qi + 8) * TT + kj)   = make_float2(s2, s3);
        }
    }
}

// ---------------- softmax stats per row (NO write-back of P) ----------------
// Row q valid in cols [0, (q|127)]. Stores (max, 1/sum) into g_st; k_av applies
// exp on the fly, so the 75MB/layer normalized-P write is eliminated.
__global__ void k_softmax_stats() {
    __shared__ float red[32];
    int row = blockIdx.x;
    int qpos = row & (TT - 1);
    int L = (qpos | 127) + 1;
    const float* r = g_S + (size_t)row * TT;
    int tid = threadIdx.x;
    float v[4], m = -1e30f;
    #pragma unroll
    for (int i = 0; i < 4; i++) {
        int c = tid + 256 * i;
        v[i] = (c < L) ? r[c] : -1e30f;
        m = fmaxf(m, v[i]);
    }
    #pragma unroll
    for (int o = 16; o; o >>= 1) m = fmaxf(m, __shfl_xor_sync(0xffffffffu, m, o));
    if ((tid & 31) == 0) red[tid >> 5] = m;
    __syncthreads();
    if (tid < 32) {
        float t = (tid < 8) ? red[tid] : -1e30f;
        #pragma unroll
        for (int o = 4; o; o >>= 1) t = fmaxf(t, __shfl_xor_sync(0xffffffffu, t, o));
        if (tid == 0) red[0] = t;
    }
    __syncthreads();
    m = red[0];
    __syncthreads();
    float s = 0.f;
    #pragma unroll
    for (int i = 0; i < 4; i++) s += __expf(v[i] - m);
    // block reduce sum
    #pragma unroll
    for (int o = 16; o; o >>= 1) s += __shfl_xor_sync(0xffffffffu, s, o);
    if ((tid & 31) == 0) red[tid >> 5] = s;
    __syncthreads();
    if (tid == 0) {
        float t = 0.f;
        #pragma unroll
        for (int i = 0; i < 8; i++) t += red[i];
        g_st[row] = make_float2(m, 1.f / t);
    }
}

// ================= tensor-core O = P @ V (exp fused into conversion) =========
#define AV_SMEM 49152

__global__ void __launch_bounds__(256, 2)
k_av_t(const float* __restrict__ v, float* __restrict__ o) {
    extern __shared__ char smem[];
    const uint32_t sb = smem_u32(smem);
    const int bh = blockIdx.y, b = bh >> 4, h = bh & 15;
    const int q0 = blockIdx.x * 128;
    const int tid = threadIdx.x, lane = tid & 31, wid = tid >> 5;
    const int wm = wid & 3, wn = wid >> 2;

    const int a_m = tid >> 3, a_kq = tid & 7;
    const int b_n = tid & 63;
    const int b_q0 = tid >> 6;
    const int b_s = (b_n >> 3) & 7;

    const int a_m_in = (lane & 7) + ((lane >> 3) & 1) * 8;
    const int a_kb   = ((lane >> 4) & 1) * 16;
    const int b_n_in = (lane & 7) + ((lane >> 4) & 1) * 8;
    const int b_kb   = ((lane >> 3) & 1) * 16;

    float acc[2][4][4];
    #pragma unroll
    for (int i = 0; i < 2; i++)
        #pragma unroll
        for (int j = 0; j < 4; j++)
            #pragma unroll
            for (int r = 0; r < 4; r++) acc[i][j][r] = 0.f;

    const int nchunk = (q0 + 128) >> 5;
    const float* Prow = g_S + ((size_t)bh * TT + q0) * TT;
    float4 pa[4], pb[2];

    // per-thread row softmax stats (rows fixed across chunks)
    float2 st[4];
    #pragma unroll
    for (int i = 0; i < 4; i++)
        st[i] = g_st[bh * TT + q0 + a_m + 32 * i];

    #define APPLY_EXP(P, S) do { \
        (P).x = __expf((P).x - (S).x) * (S).y; \
        (P).y = __expf((P).y - (S).x) * (S).y; \
        (P).z = __expf((P).z - (S).x) * (S).y; \
        (P).w = __expf((P).w - (S).x) * (S).y; \
    } while (0)

    {
        #pragma unroll
        for (int i = 0; i < 4; i++) {
            int idx = tid + 256 * i;
            int m = idx >> 3, kq = idx & 7;
            pa[i] = *(const float4*)(Prow + (size_t)m * TT + kq * 4);
            APPLY_EXP(pa[i], st[i]);
        }
        #pragma unroll
        for (int i = 0; i < 2; i++) {
            int kq = (b_q0 + 4 * i) ^ b_s;
            const float* bp = v + (size_t)(b * TT + kq * 4) * EE + h * DD + b_n;
            pb[i] = make_float4(bp[0], bp[(size_t)EE], bp[(size_t)2 * EE], bp[(size_t)3 * EE]);
        }
        #pragma unroll
        for (int i = 0; i < 4; i++) {
            int idx = tid + 256 * i;
            int m = idx >> 3, kq = idx & 7;
            uint32_t h01, l01, h23, l23;
            split2(pa[i].x, pa[i].y, h01, l01);
            split2(pa[i].z, pa[i].w, h23, l23);
            uint32_t off = (uint32_t)(m * 64 + ((kq * 8) ^ (((m >> 1) & 3) << 4)));
            *(uint2*)(smem + off)        = make_uint2(h01, h23);
            *(uint2*)(smem + 8192 + off) = make_uint2(l01, l23);
        }
        #pragma unroll
        for (int i = 0; i < 2; i++) {
            int kq = (b_q0 + 4 * i) ^ b_s;
            uint32_t h01, l01, h23, l23;
            split2(pb[i].x, pb[i].y, h01, l01);
            split2(pb[i].z, pb[i].w, h23, l23);
            uint32_t off = (uint32_t)(b_n * 64 + ((kq * 8) ^ (((b_n >> 1) & 3) << 4)));
            *(uint2*)(smem + 16384 + off) = make_uint2(h01, h23);
            *(uint2*)(smem + 20480 + off) = make_uint2(l01, l23);
        }
    }
    __syncthreads();

    for (int c = 0; c < nchunk; c++) {
        const uint32_t base = sb + (uint32_t)(c & 1) * 24576;
        const uint32_t ph = base, pl = base + 8192;
        const uint32_t vh = base + 16384, vl = base + 20480;

        if (c + 1 < nchunk) {
            int j0 = (c + 1) << 5;
            #pragma unroll
            for (int i = 0; i < 4; i++) {
                int idx = tid + 256 * i;
                int m = idx >> 3, kq = idx & 7;
                pa[i] = *(const float4*)(Prow + (size_t)m * TT + j0 + kq * 4);
                APPLY_EXP(pa[i], st[i]);
            }
            #pragma unroll
            for (int i = 0; i < 2; i++) {
                int kq = (b_q0 + 4 * i) ^ b_s;
                const float* bp = v + (size_t)(b * TT + j0 + kq * 4) * EE + h * DD + b_n;
                pb[i] = make_float4(bp[0], bp[(size_t)EE], bp[(size_t)2 * EE], bp[(size_t)3 * EE]);
            }
        }

        #pragma unroll
        for (int kt = 0; kt < 2; kt++) {
            uint32_t afh[2][4], afl[2][4], bfh[2][4], bfl[2][4];
            #pragma unroll
            for (int mt = 0; mt < 2; mt++) {
                int row = wm * 32 + mt * 16 + a_m_in;
                uint32_t off = (uint32_t)(row * 64 + ((kt * 32 + a_kb) ^ (((row >> 1) & 3) << 4)));
                ldsm_x4(afh[mt][0], afh[mt][1], afh[mt][2], afh[mt][3], ph + off);
                ldsm_x4(afl[mt][0], afl[mt][1], afl[mt][2], afl[mt][3], pl + off);
            }
            #pragma unroll
            for (int ntp = 0; ntp < 2; ntp++) {
                int row = wn * 32 + ntp * 16 + b_n_in;
                uint32_t off = (uint32_t)(row * 64 + ((kt * 32 + b_kb) ^ (((row >> 1) & 3) << 4)));
                ldsm_x4(bfh[ntp][0], bfh[ntp][1], bfh[ntp][2], bfh[ntp][3], vh + off);
                ldsm_x4(bfl[ntp][0], bfl[ntp][1], bfl[ntp][2], bfl[ntp][3], vl + off);
            }
            #pragma unroll
            for (int mt = 0; mt < 2; mt++)
                #pragma unroll
                for (int nt = 0; nt < 4; nt++) {
                    const int np = nt >> 1, ne = (nt & 1) * 2;
                    MMA3(acc[mt][nt], afh[mt], afl[mt],
                         bfh[np][ne], bfh[np][ne + 1], bfl[np][ne], bfl[np][ne + 1]);
                }
        }

        if (c + 1 < nchunk) {
            char* nb = smem + ((c + 1) & 1) * 24576;
            #pragma unroll
            for (int i = 0; i < 4; i++) {
                int idx = tid + 256 * i;
                int m = idx >> 3, kq = idx & 7;
                uint32_t h01, l01, h23, l23;
                split2(pa[i].x, pa[i].y, h01, l01);
                split2(pa[i].z, pa[i].w, h23, l23);
                uint32_t off = (uint32_t)(m * 64 + ((kq * 8) ^ (((m >> 1) & 3) << 4)));
                *(uint2*)(nb + off)        = make_uint2(h01, h23);
                *(uint2*)(nb + 8192 + off) = make_uint2(l01, l23);
            }
            #pragma unroll
            for (int i = 0; i < 2; i++) {
                int kq = (b_q0 + 4 * i) ^ b_s;
                uint32_t h01, l01, h23, l23;
                split2(pb[i].x, pb[i].y, h01, l01);
                split2(pb[i].z, pb[i].w, h23, l23);
                uint32_t off = (uint32_t)(b_n * 64 + ((kq * 8) ^ (((b_n >> 1) & 3) << 4)));
                *(uint2*)(nb + 16384 + off) = make_uint2(h01, h23);
                *(uint2*)(nb + 20480 + off) = make_uint2(l01, l23);
            }
            __syncthreads();
        }
    }

    const int row0 = lane >> 2, col0 = (lane & 3) * 2;
    #pragma unroll
    for (int mt = 0; mt < 2; mt++) {
        #pragma unroll
        for (int nt = 0; nt < 4; nt++) {
            int gm = q0 + wm * 32 + mt * 16 + row0;
            int gn = wn * 32 + nt * 8 + col0;
            size_t p0 = (size_t)(b * TT + gm) * EE + h * DD + gn;
            size_t p1 = (size_t)(b * TT + gm + 8) * EE + h * DD + gn;
            *(float2*)(o + p0) = make_float2(acc[mt][nt][0], acc[mt][nt][1]);
            *(float2*)(o + p1) = make_float2(acc[mt][nt][2], acc[mt][nt][3]);
        }
    }
}

// ---------------- embed ----------------
__global__ void k_embed(const int* __restrict__ idx, const float* __restrict__ tok,
                        const float* __restrict__ pos, float* __restrict__ x) {
    int r = blockIdx.x;
    int t = r & (TT - 1);
    int tokid = idx[r];
    const float4* te = (const float4*)(tok + (size_t)tokid * EE);
    const float4* pe = (const float4*)(pos + (size_t)t * EE);
    float4* xr = (float4*)(x + (size_t)r * EE);
    int c = threadIdx.x;
    float4 a = te[c], b = pe[c];
    xr[c] = make_float4(a.x + b.x, a.y + b.y, a.z + b.z, a.w + b.w);
}

// ---------------- block reduce ----------------
__device__ __forceinline__ float blockReduceSum(float val, float* red) {
    int tid = threadIdx.x;
    #pragma unroll
    for (int o = 16; o; o >>= 1) val += __shfl_xor_sync(0xffffffffu, val, o);
    if ((tid & 31) == 0) red[tid >> 5] = val;
    __syncthreads();
    if (tid < 32) {
        float v = (tid < 8) ? red[tid] : 0.f;
        #pragma unroll
        for (int o = 4; o; o >>= 1) v += __shfl_xor_sync(0xffffffffu, v, o);
        if (tid == 0) red[0] = v;
    }
    __syncthreads();
    float r = red[0];
    __syncthreads();
    return r;
}

// ---------------- layernorm ----------------
__global__ void k_ln(const float* __restrict__ x, const float* __restrict__ g,
                     const float* __restrict__ b, float* __restrict__ out) {
    __shared__ float red[32];
    int row = blockIdx.x, tid = threadIdx.x;
    const float* xr = x + (size_t)row * EE;
    float v[4];
    float s = 0.f;
    #pragma unroll
    for (int i = 0; i < 4; i++) { v[i] = xr[tid + 256 * i]; s += v[i]; }
    s = blockReduceSum(s, red);
    float mean = s * (1.f / EE);
    float s2 = 0.f;
    #pragma unroll
    for (int i = 0; i < 4; i++) { float d = v[i] - mean; s2 += d * d; }
    s2 = blockReduceSum(s2, red);
    float inv = rsqrtf(s2 * (1.f / EE) + 1e-5f);
    #pragma unroll
    for (int i = 0; i < 4; i++) {
        int c = tid + 256 * i;
        out[(size_t)row * EE + c] = (v[i] - mean) * inv * g[c] + b[c];
    }
}

// ---------------- host orchestration ----------------
extern "C" void kernel_launch(void* const* d_in, const int* in_sizes, int n_in,
                              void* d_out, int out_size) {
    const int*   idx  = (const int*)  d_in[0];
    const float* tok  = (const float*)d_in[1];
    const float* pos  = (const float*)d_in[2];
    const float* Wq   = (const float*)d_in[3];
    const float* Wk   = (const float*)d_in[4];
    const float* Wv   = (const float*)d_in[5];
    const float* Wp   = (const float*)d_in[6];
    const float* bp   = (const float*)d_in[7];
    const float* g1   = (const float*)d_in[8];
    const float* b1   = (const float*)d_in[9];
    const float* g2   = (const float*)d_in[10];
    const float* b2   = (const float*)d_in[11];
    const float* W1   = (const float*)d_in[12];
    const float* bf1  = (const float*)d_in[13];
    const float* W2   = (const float*)d_in[14];
    const float* bf2  = (const float*)d_in[15];
    const float* gf   = (const float*)d_in[16];
    const float* bff  = (const float*)d_in[17];
    const float* Wlm  = (const float*)d_in[18];
    const float* blm  = (const float*)d_in[19];
    float* out = (float*)d_out;

    float *x, *h, *q, *k, *v, *o, *ff;
    cudaGetSymbolAddress((void**)&x,  g_x);
    cudaGetSymbolAddress((void**)&h,  g_h);
    cudaGetSymbolAddress((void**)&q,  g_q);
    cudaGetSymbolAddress((void**)&k,  g_k);
    cudaGetSymbolAddress((void**)&v,  g_v);
    cudaGetSymbolAddress((void**)&o,  g_o);
    cudaGetSymbolAddress((void**)&ff, g_ff);

    cudaFuncSetAttribute(k_tgemm<false,false,false>,
                         cudaFuncAttributeMaxDynamicSharedMemorySize, TG_SMEM);
    cudaFuncSetAttribute(k_tgemm<true,false,true>,
                         cudaFuncAttributeMaxDynamicSharedMemorySize, TG_SMEM);
    cudaFuncSetAttribute(k_tgemm<true,true,false>,
                         cudaFuncAttributeMaxDynamicSharedMemorySize, TG_SMEM);
    cudaFuncSetAttribute(k_tgemm<true,false,false>,
                         cudaFuncAttributeMaxDynamicSharedMemorySize, TG_SMEM);
    cudaFuncSetAttribute(k_scores_t,
                         cudaFuncAttributeMaxDynamicSharedMemorySize, SC_SMEM);
    cudaFuncSetAttribute(k_av_t,
                         cudaFuncAttributeMaxDynamicSharedMemorySize, AV_SMEM);

    k_embed<<<RR, 256>>>(idx, tok, pos, x);

    // grid: x = M/128 (row tiles), y = N/64 (col tiles)
    dim3 gEE(RR / 128, EE / 64);       // (16, 16)
    dim3 gFF(RR / 128, FF / 64);       // (16, 64)
    dim3 gLM(RR / 128, VV / 64);       // (16, 500)

    for (int l = 0; l < LL; l++) {
        const float* wq = Wq + (size_t)l * EE * EE;
        const float* wk = Wk + (size_t)l * EE * EE;
        const float* wv = Wv + (size_t)l * EE * EE;
        const float* wp = Wp + (size_t)l * EE * EE;
        const float* w1 = W1 + (size_t)l * EE * FF;
        const float* w2 = W2 + (size_t)l * FF * EE;

        k_ln<<<RR, 256>>>(x, g1 + l * EE, b1 + l * EE, h);
        k_tgemm<false,false,false><<<gEE, 128, TG_SMEM>>>(h, wq, nullptr, nullptr, q, RR, EE, EE);
        k_tgemm<false,false,false><<<gEE, 128, TG_SMEM>>>(h, wk, nullptr, nullptr, k, RR, EE, EE);
        k_tgemm<false,false,false><<<gEE, 128, TG_SMEM>>>(h, wv, nullptr, nullptr, v, RR, EE, EE);

        k_scores_t<<<dim3(8, 8, 32), 512, SC_SMEM>>>(q, k);
        k_softmax_stats<<<BB * HH * TT, 256>>>();
        k_av_t<<<dim3(8, 32), 256, AV_SMEM>>>(v, o);

        // x = x + o @ Wp + bp
        k_tgemm<true,false,true><<<gEE, 128, TG_SMEM>>>(o, wp, bp + l * EE, x, x, RR, EE, EE);

        k_ln<<<RR, 256>>>(x, g2 + l * EE, b2 + l * EE, h);
        // ff = relu(h @ W1 + bf1)
        k_tgemm<true,true,false><<<gFF, 128, TG_SMEM>>>(h, w1, bf1 + l * FF, nullptr, ff, RR, FF, EE);
        // x = x + ff @ W2 + bf2
        k_tgemm<true,false,true><<<gEE, 128, TG_SMEM>>>(ff, w2, bf2 + l * EE, x, x, RR, EE, FF);
    }

    k_ln<<<RR, 256>>>(x, gf, bff, h);
    k_tgemm<true,false,false><<<gLM, 128, TG_SMEM>>>(h, Wlm, blm, nullptr, out, RR, VV, EE);
}